// round 3
// baseline (speedup 1.0000x reference)
#include <cuda_runtime.h>
#include <cstdint>
#include <math.h>

#define VOCAB  32000
#define EMBED  300
#define HIDDEN 512
#define G4     2048   // 4*HIDDEN
#define BATCH  256
#define SEQ    512
#define NOUT   7

// ---------------------------------------------------------------------------
// Device scratch (allocation-free rule: __device__ globals)
// ---------------------------------------------------------------------------
__device__ float g_gx[(size_t)SEQ * BATCH * G4];   // 1 GiB  [s][b][g]
__device__ float g_h[2][BATCH * HIDDEN];
__device__ unsigned g_cnt;
__device__ unsigned g_epoch;

// ---------------------------------------------------------------------------
// Packed f32x2 helpers
// ---------------------------------------------------------------------------
__device__ __forceinline__ unsigned long long ffma2(unsigned long long a,
                                                    unsigned long long b,
                                                    unsigned long long c) {
    unsigned long long d;
    asm("fma.rn.f32x2 %0, %1, %2, %3;" : "=l"(d) : "l"(a), "l"(b), "l"(c));
    return d;
}
__device__ __forceinline__ unsigned long long dup_f32(float x) {
    unsigned long long d;
    asm("mov.b64 %0, {%1, %1};" : "=l"(d) : "f"(x));
    return d;
}
__device__ __forceinline__ float lo_f32(unsigned long long v) {
    return __uint_as_float((unsigned)(v & 0xffffffffull));
}
__device__ __forceinline__ float hi_f32(unsigned long long v) {
    return __uint_as_float((unsigned)(v >> 32));
}
__device__ __forceinline__ float sigf(float x) {
    return 1.f / (1.f + expf(-x));
}

// ---------------------------------------------------------------------------
// Kernel A: fused embedding gather + input projection GEMM (unchanged, f32x2)
// ---------------------------------------------------------------------------
#define BM 128
#define BN 128
#define BK 16

__global__ __launch_bounds__(256, 2) void k_embed_inproj(
    const int* __restrict__ tokens, const float* __restrict__ emb,
    const float* __restrict__ W_ih, const float* __restrict__ b_ih)
{
    __shared__ float As[BK][BM];
    __shared__ float Bs[BK][BN];
    __shared__ int   tok_s[BM];

    const int n0  = blockIdx.x * BN;
    const int m0  = blockIdx.y * BM;
    const int tid = threadIdx.x;

    if (tid < BM) {
        int r = m0 + tid;
        int s = r >> 8;
        int b = r & 255;
        tok_s[tid] = tokens[b * SEQ + s];
    }
    __syncthreads();

    const int tx = tid & 15;
    const int ty = tid >> 4;

    unsigned long long acc[8][4];
    #pragma unroll
    for (int i = 0; i < 8; i++)
        #pragma unroll
        for (int j = 0; j < 4; j++) acc[i][j] = 0ull;

    for (int k0 = 0; k0 < EMBED; k0 += BK) {
        #pragma unroll
        for (int x = 0; x < 8; x++) {
            int idx = tid + x * 256;
            int m   = idx >> 4;
            int kk  = idx & 15;
            int e   = k0 + kk;
            int t   = tok_s[m];
            float v = 0.f;
            if (t != 0 && e < EMBED) v = emb[(size_t)t * EMBED + e];
            As[kk][m] = v;
        }
        #pragma unroll
        for (int x = 0; x < 8; x++) {
            int idx = tid + x * 256;
            int n   = idx >> 4;
            int kk  = idx & 15;
            int e   = k0 + kk;
            float v = 0.f;
            if (e < EMBED) v = W_ih[(size_t)(n0 + n) * EMBED + e];
            Bs[kk][n] = v;
        }
        __syncthreads();

        #pragma unroll
        for (int kk = 0; kk < BK; kk++) {
            float a[8];
            const float4* ap = (const float4*)&As[kk][ty * 8];
            float4 a0 = ap[0], a1 = ap[1];
            a[0]=a0.x; a[1]=a0.y; a[2]=a0.z; a[3]=a0.w;
            a[4]=a1.x; a[5]=a1.y; a[6]=a1.z; a[7]=a1.w;
            unsigned long long bv[4];
            const unsigned long long* bp =
                (const unsigned long long*)&Bs[kk][tx * 8];
            #pragma unroll
            for (int j = 0; j < 4; j++) bv[j] = bp[j];
            #pragma unroll
            for (int i = 0; i < 8; i++) {
                unsigned long long ad = dup_f32(a[i]);
                #pragma unroll
                for (int j = 0; j < 4; j++)
                    acc[i][j] = ffma2(ad, bv[j], acc[i][j]);
            }
        }
        __syncthreads();
    }

    float bias[8];
    #pragma unroll
    for (int j = 0; j < 8; j++) bias[j] = b_ih[n0 + tx * 8 + j];

    #pragma unroll
    for (int i = 0; i < 8; i++) {
        int r = m0 + ty * 8 + i;
        size_t base = (size_t)r * G4 + n0 + tx * 8;
        #pragma unroll
        for (int j = 0; j < 4; j++) {
            g_gx[base + 2 * j]     = lo_f32(acc[i][j]) + bias[2 * j];
            g_gx[base + 2 * j + 1] = hi_f32(acc[i][j]) + bias[2 * j + 1];
        }
    }
}

// ---------------------------------------------------------------------------
// Persistent LSTM kernel: 128 CTAs x 256 threads, one launch for all 512 steps
//
// CTA tile: 64 batches x 16 j (x 4 gates).  W_hh slice (64 g-rows x 512 k)
// resident in SMEM for the whole kernel.  c-state resident in registers.
// h exchanged through L2 (ldcg/stcg) with a grid-wide epoch barrier per step.
//
// Thread map: ks = tid>>7 (k-half), within 128: jp = t&7 (j-pair), bq = t>>3.
// Thread computes 4 b x (2 j x 4 gates) as 16 f32x2 accumulators over its
// 256-k half; halves reduced via SMEM at step end.
// ---------------------------------------------------------------------------
#define WPITCH   66          // floats per Wsm row (even -> LDS.64 aligned)
#define WPITCH64 33
#define HPITCH64 65          // u64 per Hs row (h stored duplicated as f32x2)
#define WSIZE_F  (HIDDEN * WPITCH)          // 33792 floats
#define HSIZE_F  (64 * HPITCH64 * 2)        // 8320 floats per buffer
#define SMEM_BYTES ((WSIZE_F + 2 * HSIZE_F) * 4)   // 201,728 B

__global__ __launch_bounds__(256, 1) void k_lstm_persist(
    const float* __restrict__ W_hh, const float* __restrict__ b_hh)
{
    extern __shared__ float sm[];
    float* Wsm = sm;
    float* Hs[2] = { sm + WSIZE_F, sm + WSIZE_F + HSIZE_F };
    unsigned long long* red = (unsigned long long*)(sm + WSIZE_F);

    const int tid = threadIdx.x;
    const int cta = blockIdx.x;        // 0..127
    const int b0  = (cta & 3) * 64;    // 4 b-tiles
    const int j0  = (cta >> 2) * 16;   // 32 j-tiles

    // ---- load W_hh slice into SMEM once: Wsm[k][g_local], g_local=gate*16+jl
    {
        int gl   = tid >> 2;              // 0..63
        int ks0  = (tid & 3) * 128;
        int gate = gl >> 4, jl = gl & 15;
        const float* wrow = W_hh + (size_t)(gate * HIDDEN + j0 + jl) * HIDDEN;
        for (int k = ks0; k < ks0 + 128; k++)
            Wsm[k * WPITCH + gl] = wrow[k];
    }

    const int ks = tid >> 7;       // k-half 0/1
    const int t7 = tid & 127;
    const int jp = t7 & 7;         // j-pair
    const int bq = t7 >> 3;        // 0..15 (x4 batches)

    // epilogue-resident state (ks==0 threads only)
    float creg[4][2];
    float bh[4][2];
    #pragma unroll
    for (int bb = 0; bb < 4; bb++) { creg[bb][0] = 0.f; creg[bb][1] = 0.f; }
    if (ks == 0) {
        #pragma unroll
        for (int g = 0; g < 4; g++) {
            bh[g][0] = b_hh[g * HIDDEN + j0 + jp * 2];
            bh[g][1] = b_hh[g * HIDDEN + j0 + jp * 2 + 1];
        }
    }

    const unsigned long long* W64 = (const unsigned long long*)Wsm;

    for (int s = 0; s < SEQ; s++) {
        const float* __restrict__ h_in  = g_h[s & 1];
        float* __restrict__       h_out = g_h[(s & 1) ^ 1];

        unsigned long long acc[4][4];
        #pragma unroll
        for (int bb = 0; bb < 4; bb++)
            #pragma unroll
            for (int g = 0; g < 4; g++) acc[bb][g] = 0ull;

        // stage chunk 0
        {
            unsigned long long* bufd = (unsigned long long*)Hs[0];
            #pragma unroll
            for (int x = 0; x < 16; x++) {
                int idx = x * 256 + tid;
                int b   = idx >> 6, kk = idx & 63;
                float v = __ldcg(h_in + (size_t)(b0 + b) * HIDDEN + kk);
                bufd[kk * HPITCH64 + b] = dup_f32(v);
            }
        }
        __syncthreads();

        for (int c = 0; c < 8; c++) {
            const unsigned long long* H64 =
                (const unsigned long long*)Hs[c & 1];
            if (c < 7) {
                unsigned long long* bufd =
                    (unsigned long long*)Hs[(c + 1) & 1];
                int kbase = (c + 1) * 64;
                #pragma unroll
                for (int x = 0; x < 16; x++) {
                    int idx = x * 256 + tid;
                    int b   = idx >> 6, kk = idx & 63;
                    float v = __ldcg(h_in + (size_t)(b0 + b) * HIDDEN +
                                     kbase + kk);
                    bufd[kk * HPITCH64 + b] = dup_f32(v);
                }
            }

            #pragma unroll 4
            for (int kk = 0; kk < 32; kk++) {
                int kl = ks * 32 + kk;
                int kg = c * 64 + kl;
                const unsigned long long* wr = W64 + (size_t)kg * WPITCH64;
                unsigned long long w0 = wr[jp];
                unsigned long long w1 = wr[8 + jp];
                unsigned long long w2 = wr[16 + jp];
                unsigned long long w3 = wr[24 + jp];
                const unsigned long long* hr =
                    H64 + (size_t)kl * HPITCH64 + bq * 4;
                #pragma unroll
                for (int bb = 0; bb < 4; bb++) {
                    unsigned long long hd = hr[bb];
                    acc[bb][0] = ffma2(hd, w0, acc[bb][0]);
                    acc[bb][1] = ffma2(hd, w1, acc[bb][1]);
                    acc[bb][2] = ffma2(hd, w2, acc[bb][2]);
                    acc[bb][3] = ffma2(hd, w3, acc[bb][3]);
                }
            }
            __syncthreads();
        }

        // k-split reduction: ks==1 dumps partials, ks==0 folds + epilogue
        if (ks == 1) {
            #pragma unroll
            for (int bb = 0; bb < 4; bb++)
                #pragma unroll
                for (int g = 0; g < 4; g++)
                    red[(bb * 4 + g) * 128 + t7] = acc[bb][g];
        }
        __syncthreads();

        if (ks == 0) {
            #pragma unroll
            for (int bb = 0; bb < 4; bb++) {
                int b = b0 + bq * 4 + bb;
                const float* gxp = g_gx + ((size_t)s * BATCH + b) * G4 +
                                   j0 + jp * 2;
                float ga[4][2];
                #pragma unroll
                for (int g = 0; g < 4; g++) {
                    unsigned long long r = red[(bb * 4 + g) * 128 + t7];
                    ga[g][0] = lo_f32(acc[bb][g]) + lo_f32(r) +
                               __ldg(gxp + g * HIDDEN)     + bh[g][0];
                    ga[g][1] = hi_f32(acc[bb][g]) + hi_f32(r) +
                               __ldg(gxp + g * HIDDEN + 1) + bh[g][1];
                }
                float2 hv;
                #pragma unroll
                for (int jj = 0; jj < 2; jj++) {
                    float ig = sigf(ga[0][jj]);
                    float fg = sigf(ga[1][jj]);
                    float gv = tanhf(ga[2][jj]);
                    float og = sigf(ga[3][jj]);
                    float cn = fg * creg[bb][jj] + ig * gv;
                    creg[bb][jj] = cn;
                    float hn = og * tanhf(cn);
                    if (jj == 0) hv.x = hn; else hv.y = hn;
                }
                __stcg((float2*)(h_out + (size_t)b * HIDDEN + j0 + jp * 2),
                       hv);
            }
        }

        // ---- grid-wide epoch barrier ----
        __syncthreads();
        if (tid == 0) {
            __threadfence();
            unsigned a = atomicAdd(&g_cnt, 1u);
            if (a == gridDim.x - 1) {
                g_cnt = 0;
                __threadfence();
                *(volatile unsigned*)&g_epoch = (unsigned)(s + 1);
            } else {
                while (*(volatile unsigned*)&g_epoch < (unsigned)(s + 1)) { }
            }
            __threadfence();
        }
        __syncthreads();
    }
}

// ---------------------------------------------------------------------------
// Init: zero h0 and barrier state
// ---------------------------------------------------------------------------
__global__ void k_init() {
    int i = blockIdx.x * blockDim.x + threadIdx.x;
    if (i < BATCH * HIDDEN) g_h[0][i] = 0.f;
    if (i == 0) { g_cnt = 0u; g_epoch = 0u; }
}

// ---------------------------------------------------------------------------
// Kernel C: logits = h_T @ W_fc^T + b_fc  (h_T in g_h[0] after 512 steps)
// ---------------------------------------------------------------------------
__global__ __launch_bounds__(128) void k_fc(
    const float* __restrict__ W_fc, const float* __restrict__ b_fc,
    float* __restrict__ out)
{
    const int b   = blockIdx.x;
    const int tid = threadIdx.x;
    const float* __restrict__ h = g_h[0];

    float p[NOUT];
    #pragma unroll
    for (int o = 0; o < NOUT; o++) p[o] = 0.f;

    for (int jj = tid; jj < HIDDEN; jj += 128) {
        float hv = h[b * HIDDEN + jj];
        #pragma unroll
        for (int o = 0; o < NOUT; o++) p[o] += hv * W_fc[o * HIDDEN + jj];
    }

    __shared__ float redm[NOUT][128];
    #pragma unroll
    for (int o = 0; o < NOUT; o++) redm[o][tid] = p[o];
    __syncthreads();
    for (int st = 64; st > 0; st >>= 1) {
        if (tid < st) {
            #pragma unroll
            for (int o = 0; o < NOUT; o++) redm[o][tid] += redm[o][tid + st];
        }
        __syncthreads();
    }
    if (tid < NOUT) out[b * NOUT + tid] = redm[tid][0] + b_fc[tid];
}

// ---------------------------------------------------------------------------
// Launch
// ---------------------------------------------------------------------------
extern "C" void kernel_launch(void* const* d_in, const int* in_sizes, int n_in,
                              void* d_out, int out_size)
{
    const int*   tokens = (const int*)  d_in[0];
    const float* emb    = (const float*)d_in[1];
    const float* W_ih   = (const float*)d_in[2];
    const float* b_ih   = (const float*)d_in[3];
    const float* W_hh   = (const float*)d_in[4];
    const float* b_hh   = (const float*)d_in[5];
    const float* W_fc   = (const float*)d_in[6];
    const float* b_fc   = (const float*)d_in[7];
    float* out = (float*)d_out;

    static bool attr_set = false;
    if (!attr_set) {
        cudaFuncSetAttribute(k_lstm_persist,
                             cudaFuncAttributeMaxDynamicSharedMemorySize,
                             SMEM_BYTES);
        attr_set = true;
    }

    k_init<<<(BATCH * HIDDEN + 255) / 256, 256>>>();

    dim3 gA(G4 / BN, (BATCH * SEQ) / BM);   // (16, 1024)
    k_embed_inproj<<<gA, 256>>>(tokens, emb, W_ih, b_ih);

    k_lstm_persist<<<128, 256, SMEM_BYTES>>>(W_hh, b_hh);

    k_fc<<<BATCH, 128>>>(W_fc, b_fc, out);
}

// round 4
// speedup vs baseline: 2.6994x; 2.6994x over previous
#include <cuda_runtime.h>
#include <cstdint>
#include <math.h>

#define VOCAB  32000
#define EMBED  300
#define HIDDEN 512
#define G4     2048   // 4*HIDDEN
#define BATCH  256
#define SEQ    512
#define NOUT   7

// ---------------------------------------------------------------------------
// Device scratch (allocation-free rule: __device__ globals)
// ---------------------------------------------------------------------------
__device__ float g_gx[(size_t)SEQ * BATCH * G4];   // 1 GiB  [s][b][g]
__device__ float g_h[2][BATCH * HIDDEN];
__device__ float g_c[BATCH * HIDDEN];              // in-place cell state

// ---------------------------------------------------------------------------
// Packed f32x2 helpers
// ---------------------------------------------------------------------------
__device__ __forceinline__ unsigned long long ffma2(unsigned long long a,
                                                    unsigned long long b,
                                                    unsigned long long c) {
    unsigned long long d;
    asm("fma.rn.f32x2 %0, %1, %2, %3;" : "=l"(d) : "l"(a), "l"(b), "l"(c));
    return d;
}
__device__ __forceinline__ unsigned long long dup_f32(float x) {
    unsigned long long d;
    asm("mov.b64 %0, {%1, %1};" : "=l"(d) : "f"(x));
    return d;
}
__device__ __forceinline__ float lo_f32(unsigned long long v) {
    return __uint_as_float((unsigned)(v & 0xffffffffull));
}
__device__ __forceinline__ float hi_f32(unsigned long long v) {
    return __uint_as_float((unsigned)(v >> 32));
}
__device__ __forceinline__ float sigf(float x) {
    return 1.f / (1.f + expf(-x));
}

// ---------------------------------------------------------------------------
// Kernel A: fused embedding gather + input projection GEMM (unchanged)
// ---------------------------------------------------------------------------
#define BM 128
#define BN 128
#define BK 16

__global__ __launch_bounds__(256, 2) void k_embed_inproj(
    const int* __restrict__ tokens, const float* __restrict__ emb,
    const float* __restrict__ W_ih, const float* __restrict__ b_ih)
{
    __shared__ float As[BK][BM];
    __shared__ float Bs[BK][BN];
    __shared__ int   tok_s[BM];

    const int n0  = blockIdx.x * BN;
    const int m0  = blockIdx.y * BM;
    const int tid = threadIdx.x;

    if (tid < BM) {
        int r = m0 + tid;
        int s = r >> 8;
        int b = r & 255;
        tok_s[tid] = tokens[b * SEQ + s];
    }
    __syncthreads();

    const int tx = tid & 15;
    const int ty = tid >> 4;

    unsigned long long acc[8][4];
    #pragma unroll
    for (int i = 0; i < 8; i++)
        #pragma unroll
        for (int j = 0; j < 4; j++) acc[i][j] = 0ull;

    for (int k0 = 0; k0 < EMBED; k0 += BK) {
        #pragma unroll
        for (int x = 0; x < 8; x++) {
            int idx = tid + x * 256;
            int m   = idx >> 4;
            int kk  = idx & 15;
            int e   = k0 + kk;
            int t   = tok_s[m];
            float v = 0.f;
            if (t != 0 && e < EMBED) v = emb[(size_t)t * EMBED + e];
            As[kk][m] = v;
        }
        #pragma unroll
        for (int x = 0; x < 8; x++) {
            int idx = tid + x * 256;
            int n   = idx >> 4;
            int kk  = idx & 15;
            int e   = k0 + kk;
            float v = 0.f;
            if (e < EMBED) v = W_ih[(size_t)(n0 + n) * EMBED + e];
            Bs[kk][n] = v;
        }
        __syncthreads();

        #pragma unroll
        for (int kk = 0; kk < BK; kk++) {
            float a[8];
            const float4* ap = (const float4*)&As[kk][ty * 8];
            float4 a0 = ap[0], a1 = ap[1];
            a[0]=a0.x; a[1]=a0.y; a[2]=a0.z; a[3]=a0.w;
            a[4]=a1.x; a[5]=a1.y; a[6]=a1.z; a[7]=a1.w;
            unsigned long long bv[4];
            const unsigned long long* bp =
                (const unsigned long long*)&Bs[kk][tx * 8];
            #pragma unroll
            for (int j = 0; j < 4; j++) bv[j] = bp[j];
            #pragma unroll
            for (int i = 0; i < 8; i++) {
                unsigned long long ad = dup_f32(a[i]);
                #pragma unroll
                for (int j = 0; j < 4; j++)
                    acc[i][j] = ffma2(ad, bv[j], acc[i][j]);
            }
        }
        __syncthreads();
    }

    float bias[8];
    #pragma unroll
    for (int j = 0; j < 8; j++) bias[j] = b_ih[n0 + tx * 8 + j];

    #pragma unroll
    for (int i = 0; i < 8; i++) {
        int r = m0 + ty * 8 + i;
        size_t base = (size_t)r * G4 + n0 + tx * 8;
        #pragma unroll
        for (int j = 0; j < 4; j++) {
            g_gx[base + 2 * j]     = lo_f32(acc[i][j]) + bias[2 * j];
            g_gx[base + 2 * j + 1] = hi_f32(acc[i][j]) + bias[2 * j + 1];
        }
    }
}

// ---------------------------------------------------------------------------
// Kernel B: one LSTM timestep, f32x2, k-split-2.
//
// CTA tile: 64 batches x 16 j (x4 gates).  Grid (32 j-tiles, 4 b-tiles)=128.
// 256 threads: ks = tid>>7 (k-half), t7 = tid&127: jp = t7&7 (j-pair),
// bq = t7>>3 (16 groups x 4 batches).  Per k: 4 LDS.64 (W j-pairs for 4
// gates) + 4 scalar h loads (broadcast) + 4 dup-MOVs + 16 FFMA2.
// Register-staged double buffering: LDG chunk c+1 into regs while computing
// chunk c from SMEM.  KC=64 -> 8 chunks, 16 bars/step.
// ---------------------------------------------------------------------------
#define KC 64

__global__ __launch_bounds__(256, 1) void k_step(
    int s, const float* __restrict__ W_hh, const float* __restrict__ b_hh)
{
    // W: [kk][g_local] pitch 66 (even -> LDS.64-aligned rows, 2-way STS ok)
    // H: [kk][b]       pitch 65 (STS conflict-free: bank = kk + b)
    __shared__ __align__(16) float Wsm[KC][66];     // 16,896 B
    __shared__ float Hs[KC][65];                    // 16,640 B

    const float* __restrict__ h_in  = g_h[s & 1];
    float* __restrict__       h_out = g_h[(s & 1) ^ 1];

    const int j0  = blockIdx.x * 16;   // 32 j-tiles
    const int b0  = blockIdx.y * 64;   // 4 b-tiles
    const int tid = threadIdx.x;
    const int ks  = tid >> 7;          // k-half
    const int t7  = tid & 127;
    const int jp  = t7 & 7;            // j-pair within 16 j
    const int bq  = t7 >> 3;           // 0..15, 4 batches each

    // staging-load index map (coalesced LDG): idx = tid + x*256
    const int sg_row = tid >> 6;       // 0..3  (row block, +4 per x)
    const int sg_kk  = tid & 63;       // k within chunk

    // ---- epilogue operand prefetch (ks==0 threads), overlaps the GEMM ----
    float gxv[4][4][2], cv[4][2], bh[4][2];
    if (ks == 0) {
        #pragma unroll
        for (int g = 0; g < 4; g++) {
            const float2 bv = *(const float2*)&b_hh[g * HIDDEN + j0 + jp * 2];
            bh[g][0] = bv.x; bh[g][1] = bv.y;
        }
        #pragma unroll
        for (int bb = 0; bb < 4; bb++) {
            int b = b0 + bq * 4 + bb;
            const float* gxp = g_gx + ((size_t)s * BATCH + b) * G4 +
                               j0 + jp * 2;
            #pragma unroll
            for (int g = 0; g < 4; g++) {
                const float2 gv = *(const float2*)(gxp + g * HIDDEN);
                gxv[bb][g][0] = gv.x; gxv[bb][g][1] = gv.y;
            }
            const float2 cvv = *(const float2*)&g_c[b * HIDDEN + j0 + jp * 2];
            cv[bb][0] = cvv.x; cv[bb][1] = cvv.y;
        }
    }

    unsigned long long acc[4][4];
    #pragma unroll
    for (int bb = 0; bb < 4; bb++)
        #pragma unroll
        for (int g = 0; g < 4; g++) acc[bb][g] = 0ull;

    float wreg[16], hreg[16];

    // prologue: load chunk 0 into registers
    #pragma unroll
    for (int x = 0; x < 16; x++) {
        int gl   = sg_row + x * 4;                 // 0..63
        int gate = gl >> 4, jl = gl & 15;
        wreg[x] = W_hh[(size_t)(gate * HIDDEN + j0 + jl) * HIDDEN + sg_kk];
        hreg[x] = h_in[(size_t)(b0 + gl) * HIDDEN + sg_kk];
    }

    for (int c = 0; c < HIDDEN / KC; c++) {
        __syncthreads();               // smem free (prev chunk consumed)
        #pragma unroll
        for (int x = 0; x < 16; x++) {
            int gl = sg_row + x * 4;
            Wsm[sg_kk][gl] = wreg[x];
            Hs[sg_kk][gl]  = hreg[x];
        }
        __syncthreads();

        if (c < HIDDEN / KC - 1) {
            int kb = (c + 1) * KC + sg_kk;
            #pragma unroll
            for (int x = 0; x < 16; x++) {
                int gl   = sg_row + x * 4;
                int gate = gl >> 4, jl = gl & 15;
                wreg[x] = W_hh[(size_t)(gate * HIDDEN + j0 + jl) * HIDDEN + kb];
                hreg[x] = h_in[(size_t)(b0 + gl) * HIDDEN + kb];
            }
        }

        #pragma unroll 8
        for (int kk = 0; kk < KC / 2; kk++) {
            int kl = ks * (KC / 2) + kk;
            const unsigned long long* wr =
                (const unsigned long long*)&Wsm[kl][0];
            unsigned long long w0 = wr[jp];
            unsigned long long w1 = wr[8 + jp];
            unsigned long long w2 = wr[16 + jp];
            unsigned long long w3 = wr[24 + jp];
            const float* hrow = &Hs[kl][bq * 4];
            #pragma unroll
            for (int bb = 0; bb < 4; bb++) {
                unsigned long long hd = dup_f32(hrow[bb]);
                acc[bb][0] = ffma2(hd, w0, acc[bb][0]);
                acc[bb][1] = ffma2(hd, w1, acc[bb][1]);
                acc[bb][2] = ffma2(hd, w2, acc[bb][2]);
                acc[bb][3] = ffma2(hd, w3, acc[bb][3]);
            }
        }
    }

    // ---- k-split reduction: ks==1 dumps partials over Wsm, ks==0 folds ----
    __syncthreads();
    unsigned long long* red = (unsigned long long*)&Wsm[0][0];  // 16 KB
    if (ks == 1) {
        #pragma unroll
        for (int bb = 0; bb < 4; bb++)
            #pragma unroll
            for (int g = 0; g < 4; g++)
                red[(bb * 4 + g) * 128 + t7] = acc[bb][g];
    }
    __syncthreads();

    if (ks == 0) {
        #pragma unroll
        for (int bb = 0; bb < 4; bb++) {
            int b = b0 + bq * 4 + bb;
            float ga[4][2];
            #pragma unroll
            for (int g = 0; g < 4; g++) {
                unsigned long long r = red[(bb * 4 + g) * 128 + t7];
                ga[g][0] = lo_f32(acc[bb][g]) + lo_f32(r) +
                           gxv[bb][g][0] + bh[g][0];
                ga[g][1] = hi_f32(acc[bb][g]) + hi_f32(r) +
                           gxv[bb][g][1] + bh[g][1];
            }
            float2 hv, cvo;
            #pragma unroll
            for (int jj = 0; jj < 2; jj++) {
                float ig = sigf(ga[0][jj]);
                float fg = sigf(ga[1][jj]);
                float gv = tanhf(ga[2][jj]);
                float og = sigf(ga[3][jj]);
                float cn = fg * cv[bb][jj] + ig * gv;
                float hn = og * tanhf(cn);
                if (jj == 0) { hv.x = hn; cvo.x = cn; }
                else         { hv.y = hn; cvo.y = cn; }
            }
            *(float2*)&g_c[b * HIDDEN + j0 + jp * 2]   = cvo;
            *(float2*)&h_out[(size_t)b * HIDDEN + j0 + jp * 2] = hv;
        }
    }
}

// ---------------------------------------------------------------------------
// Init: zero h0 and c0
// ---------------------------------------------------------------------------
__global__ void k_init() {
    int i = blockIdx.x * blockDim.x + threadIdx.x;
    if (i < BATCH * HIDDEN) {
        g_h[0][i] = 0.f;
        g_c[i]    = 0.f;
    }
}

// ---------------------------------------------------------------------------
// Kernel C: logits = h_T @ W_fc^T + b_fc  (h_T in g_h[0] after 512 steps)
// ---------------------------------------------------------------------------
__global__ __launch_bounds__(128) void k_fc(
    const float* __restrict__ W_fc, const float* __restrict__ b_fc,
    float* __restrict__ out)
{
    const int b   = blockIdx.x;
    const int tid = threadIdx.x;
    const float* __restrict__ h = g_h[0];

    float p[NOUT];
    #pragma unroll
    for (int o = 0; o < NOUT; o++) p[o] = 0.f;

    for (int jj = tid; jj < HIDDEN; jj += 128) {
        float hv = h[b * HIDDEN + jj];
        #pragma unroll
        for (int o = 0; o < NOUT; o++) p[o] += hv * W_fc[o * HIDDEN + jj];
    }

    __shared__ float redm[NOUT][128];
    #pragma unroll
    for (int o = 0; o < NOUT; o++) redm[o][tid] = p[o];
    __syncthreads();
    for (int st = 64; st > 0; st >>= 1) {
        if (tid < st) {
            #pragma unroll
            for (int o = 0; o < NOUT; o++) redm[o][tid] += redm[o][tid + st];
        }
        __syncthreads();
    }
    if (tid < NOUT) out[b * NOUT + tid] = redm[tid][0] + b_fc[tid];
}

// ---------------------------------------------------------------------------
// Launch
// ---------------------------------------------------------------------------
extern "C" void kernel_launch(void* const* d_in, const int* in_sizes, int n_in,
                              void* d_out, int out_size)
{
    const int*   tokens = (const int*)  d_in[0];
    const float* emb    = (const float*)d_in[1];
    const float* W_ih   = (const float*)d_in[2];
    const float* b_ih   = (const float*)d_in[3];
    const float* W_hh   = (const float*)d_in[4];
    const float* b_hh   = (const float*)d_in[5];
    const float* W_fc   = (const float*)d_in[6];
    const float* b_fc   = (const float*)d_in[7];
    float* out = (float*)d_out;

    k_init<<<(BATCH * HIDDEN + 255) / 256, 256>>>();

    dim3 gA(G4 / BN, (BATCH * SEQ) / BM);   // (16, 1024)
    k_embed_inproj<<<gA, 256>>>(tokens, emb, W_ih, b_ih);

    dim3 gB(HIDDEN / 16, BATCH / 64);       // (32, 4) = 128 CTAs
    for (int s = 0; s < SEQ; s++)
        k_step<<<gB, 256>>>(s, W_hh, b_hh);

    k_fc<<<BATCH, 128>>>(W_fc, b_fc, out);
}